// round 4
// baseline (speedup 1.0000x reference)
#include <cuda_runtime.h>

#define NROWS 128
#define LEN   2048
#define NK    6
#define NT    256
#define SPLIT 4
#define NB    (NROWS * SPLIT)

// pad one float4 per 8 entries: lane stride in the scan becomes 144B -> conflict-free
#define PIDX(i) ((i) + ((i) >> 3))

__device__ float        g_partials[NB];
__device__ unsigned int g_count = 0;

__device__ __forceinline__ float4 f4add(float4 a, float4 b) {
    return make_float4(a.x + b.x, a.y + b.y, a.z + b.z, a.w + b.w);
}

__global__ void __launch_bounds__(NT, SPLIT) entropy_fused(
    const float* __restrict__ in, const float* __restrict__ tg, float* __restrict__ out)
{
    // P[PIDX(i)] = inclusive prefix over elements < i of (e^a, a e^a, e^b, b e^b)
    __shared__ float4 P[PIDX(LEN) + 2];
    __shared__ float4 wtot[NT / 32];
    __shared__ float  redk[NT / 32];
    __shared__ int    lastFlag;

    const int tid  = threadIdx.x;
    const int lane = tid & 31, wid = tid >> 5;
    const int bid  = blockIdx.x;
    const int row  = bid >> 2;
    const int part = bid & 3;

    // ---- load 8 consecutive elements per thread (2 float4 per tensor) ----
    const float4* in4 = (const float4*)(in + (size_t)row * LEN);
    const float4* tg4 = (const float4*)(tg + (size_t)row * LEN);
    float4 A0 = in4[2 * tid], A1 = in4[2 * tid + 1];
    float4 B0 = tg4[2 * tid], B1 = tg4[2 * tid + 1];
    const float ax[8] = {A0.x, A0.y, A0.z, A0.w, A1.x, A1.y, A1.z, A1.w};
    const float bx[8] = {B0.x, B0.y, B0.z, B0.w, B1.x, B1.y, B1.z, B1.w};

    // sequential local prefix, written to padded smem (values N(0,1): no overflow)
    float4 run = make_float4(0.f, 0.f, 0.f, 0.f);
    #pragma unroll
    for (int j = 0; j < 8; j++) {
        float ea = __expf(ax[j]);
        float eb = __expf(bx[j]);
        run.x += ea;        run.y += ax[j] * ea;
        run.z += eb;        run.w += bx[j] * eb;
        P[PIDX(8 * tid + j + 1)] = run;
    }

    // warp inclusive scan of per-thread totals
    float4 t = run;
    #pragma unroll
    for (int off = 1; off < 32; off <<= 1) {
        float4 n;
        n.x = __shfl_up_sync(0xffffffffu, t.x, off);
        n.y = __shfl_up_sync(0xffffffffu, t.y, off);
        n.z = __shfl_up_sync(0xffffffffu, t.z, off);
        n.w = __shfl_up_sync(0xffffffffu, t.w, off);
        if (lane >= off) t = f4add(t, n);
    }
    if (lane == 31) wtot[wid] = t;
    __syncthreads();
    if (wid == 0) {
        float4 w = (lane < NT / 32) ? wtot[lane] : make_float4(0.f, 0.f, 0.f, 0.f);
        #pragma unroll
        for (int off = 1; off < NT / 32; off <<= 1) {
            float4 n;
            n.x = __shfl_up_sync(0xffffffffu, w.x, off);
            n.y = __shfl_up_sync(0xffffffffu, w.y, off);
            n.z = __shfl_up_sync(0xffffffffu, w.z, off);
            n.w = __shfl_up_sync(0xffffffffu, w.w, off);
            if (lane >= off) w = f4add(w, n);
        }
        if (lane < NT / 32) wtot[lane] = w;
    }
    __syncthreads();
    {
        float4 woff = (wid > 0) ? wtot[wid - 1] : make_float4(0.f, 0.f, 0.f, 0.f);
        float4 ex = make_float4(woff.x + t.x - run.x, woff.y + t.y - run.y,
                                woff.z + t.z - run.z, woff.w + t.w - run.w);
        #pragma unroll
        for (int j = 0; j < 8; j++) {
            int p = PIDX(8 * tid + j + 1);
            P[p] = f4add(P[p], ex);
        }
        if (tid == 0) P[PIDX(0)] = make_float4(0.f, 0.f, 0.f, 0.f);
    }
    __syncthreads();

    // ---- windows: this block handles every 4th NT-stripe of each k ----
    float acc = 0.0f;
    #pragma unroll
    for (int kk = 0; kk < NK; kk++) {
        const int   k  = 4 << kk;
        const int   nW = LEN - k + 1;
        const float wk = 1.0f / (128.0f * (float)nW);
        float acck = 0.0f;
        for (int s = tid + part * NT; s < nW; s += NT * SPLIT) {
            float4 lo = P[PIDX(s)];
            float4 hi = P[PIDX(s + k)];
            float z1 = hi.x - lo.x, f1 = hi.y - lo.y;
            float z2 = hi.z - lo.z, f2 = hi.w - lo.w;
            // ent1 - ent2 = (S1*Z2 - S2*Z1)*r - log(Z1^2 * r), r = 1/(Z1*Z2)
            float r = __fdividef(1.0f, z1 * z2);
            float d = fmaf(f1 * z2 - f2 * z1, r, -__logf(z1 * z1 * r));
            acck += fabsf(d);
        }
        acc = fmaf(acck, wk, acc);
    }

    // ---- block reduce ----
    #pragma unroll
    for (int off = 16; off; off >>= 1) acc += __shfl_down_sync(0xffffffffu, acc, off);
    if (lane == 0) redk[wid] = acc;
    __syncthreads();
    if (tid == 0) {
        float s = 0.f;
        #pragma unroll
        for (int w = 0; w < NT / 32; w++) s += redk[w];
        g_partials[bid] = s;
        __threadfence();
        unsigned prev = atomicAdd(&g_count, 1u);
        lastFlag = (prev == NB - 1);
    }
    __syncthreads();

    // ---- last block: deterministic fixed-order final sum ----
    if (lastFlag) {
        volatile const float* vp = g_partials;
        if (wid == 0) {
            double s = 0.0;
            for (int i = lane; i < NB; i += 32) s += (double)vp[i];
            #pragma unroll
            for (int off = 16; off; off >>= 1) s += __shfl_down_sync(0xffffffffu, s, off);
            if (lane == 0) { out[0] = (float)s; g_count = 0; }
        }
    }
}

extern "C" void kernel_launch(void* const* d_in, const int* in_sizes, int n_in,
                              void* d_out, int out_size) {
    const float* in = (const float*)d_in[0];
    const float* tg = (const float*)d_in[1];
    entropy_fused<<<NB, NT>>>(in, tg, (float*)d_out);
}

// round 5
// speedup vs baseline: 1.2973x; 1.2973x over previous
#include <cuda_runtime.h>

#define NROWS 128
#define LEN   2048
#define NK    6
#define NT    1024

__device__ float        g_partials[NROWS];
__device__ unsigned int g_count = 0;

__device__ __forceinline__ float4 f4add(float4 a, float4 b) {
    return make_float4(a.x + b.x, a.y + b.y, a.z + b.z, a.w + b.w);
}

// FMA-pipe ln(x) for x > 0 (cephes-style). abs err ~1e-7. Keeps XU free for RCP.
__device__ __forceinline__ float fast_logf(float x) {
    int ib = __float_as_int(x);
    int e  = (ib - 0x3F3504F3) >> 23;              // mantissa into [~0.7071, 1.4142)
    float m = __int_as_float(ib - (e << 23));
    float f = m - 1.0f;
    float z = f * f;
    float p =            7.0376836292e-2f;
    p = fmaf(p, f, -1.1514610310e-1f);
    p = fmaf(p, f,  1.1676998740e-1f);
    p = fmaf(p, f, -1.2420140846e-1f);
    p = fmaf(p, f,  1.4249322787e-1f);
    p = fmaf(p, f, -1.6668057665e-1f);
    p = fmaf(p, f,  2.0000714765e-1f);
    p = fmaf(p, f, -2.4999993993e-1f);
    p = fmaf(p, f,  3.3333331174e-1f);
    p = p * f * z;                                  // f^3 * P(f)
    p = fmaf(-0.5f, z, p);
    return fmaf((float)e, 0.69314718056f, f + p);
}

__global__ void __launch_bounds__(NT, 1) entropy_fused(
    const float* __restrict__ in, const float* __restrict__ tg, float* __restrict__ out)
{
    // P[i] = inclusive prefix over elements < i of (e^a, a e^a, e^b, b e^b)
    __shared__ float4 P[LEN + 1];
    __shared__ float4 wtot[NT / 32];
    __shared__ float  redk[NT / 32];
    __shared__ int    lastFlag;

    const int tid  = threadIdx.x;
    const int lane = tid & 31, wid = tid >> 5;
    const int row  = blockIdx.x;

    // ---- 2 consecutive elements per thread ----
    const float2 a2 = ((const float2*)(in + (size_t)row * LEN))[tid];
    const float2 b2 = ((const float2*)(tg + (size_t)row * LEN))[tid];
    float e0 = __expf(a2.x), e1 = __expf(a2.y);
    float g0 = __expf(b2.x), g1 = __expf(b2.y);
    float4 v0 = make_float4(e0, a2.x * e0, g0, b2.x * g0);
    float4 v1 = f4add(make_float4(e1, a2.y * e1, g1, b2.y * g1), v0);  // local inclusive

    // warp inclusive scan of per-thread totals
    float4 t = v1;
    #pragma unroll
    for (int off = 1; off < 32; off <<= 1) {
        float4 n;
        n.x = __shfl_up_sync(0xffffffffu, t.x, off);
        n.y = __shfl_up_sync(0xffffffffu, t.y, off);
        n.z = __shfl_up_sync(0xffffffffu, t.z, off);
        n.w = __shfl_up_sync(0xffffffffu, t.w, off);
        if (lane >= off) t = f4add(t, n);
    }
    if (lane == 31) wtot[wid] = t;
    __syncthreads();
    if (wid == 0) {                 // scan 32 warp totals in one warp
        float4 w = wtot[lane];
        #pragma unroll
        for (int off = 1; off < 32; off <<= 1) {
            float4 n;
            n.x = __shfl_up_sync(0xffffffffu, w.x, off);
            n.y = __shfl_up_sync(0xffffffffu, w.y, off);
            n.z = __shfl_up_sync(0xffffffffu, w.z, off);
            n.w = __shfl_up_sync(0xffffffffu, w.w, off);
            if (lane >= off) w = f4add(w, n);
        }
        wtot[lane] = w;
    }
    __syncthreads();
    {
        float4 woff = (wid > 0) ? wtot[wid - 1] : make_float4(0.f, 0.f, 0.f, 0.f);
        float4 ex = make_float4(woff.x + t.x - v1.x, woff.y + t.y - v1.y,
                                woff.z + t.z - v1.z, woff.w + t.w - v1.w);
        P[2 * tid + 1] = f4add(v0, ex);
        P[2 * tid + 2] = f4add(v1, ex);
        if (tid == 0) P[0] = make_float4(0.f, 0.f, 0.f, 0.f);
    }
    __syncthreads();

    // ---- windows: all 6 kernel widths off the same prefix ----
    float acc = 0.0f;
    #pragma unroll
    for (int kk = 0; kk < NK; kk++) {
        const int   k  = 4 << kk;
        const int   nW = LEN - k + 1;
        const float wk = 1.0f / (128.0f * (float)nW);
        float acck = 0.0f;
        for (int s = tid; s < nW; s += NT) {
            float4 lo = P[s];
            float4 hi = P[s + k];
            float z1 = hi.x - lo.x, f1 = hi.y - lo.y;
            float z2 = hi.z - lo.z, f2 = hi.w - lo.w;
            // ent1 - ent2 = (S1*Z2 - S2*Z1)*r - log(Z1^2 * r), r = 1/(Z1*Z2)
            float r = __fdividef(1.0f, z1 * z2);                 // XU: 1 RCP
            float d = fmaf(f1 * z2 - f2 * z1, r, -fast_logf(z1 * z1 * r));  // FMA pipe
            acck += fabsf(d);
        }
        acc = fmaf(acck, wk, acc);
    }

    // ---- block reduce ----
    #pragma unroll
    for (int off = 16; off; off >>= 1) acc += __shfl_down_sync(0xffffffffu, acc, off);
    if (lane == 0) redk[wid] = acc;
    __syncthreads();
    if (wid == 0) {
        float s = redk[lane];
        #pragma unroll
        for (int off = 16; off; off >>= 1) s += __shfl_down_sync(0xffffffffu, s, off);
        if (lane == 0) {
            g_partials[row] = s;
            __threadfence();
            unsigned prev = atomicAdd(&g_count, 1u);
            lastFlag = (prev == NROWS - 1);
        }
    }
    __syncthreads();

    // ---- last block: deterministic fixed-order final sum ----
    if (lastFlag) {
        volatile const float* vp = g_partials;
        if (wid == 0) {
            double s = 0.0;
            for (int i = lane; i < NROWS; i += 32) s += (double)vp[i];
            #pragma unroll
            for (int off = 16; off; off >>= 1) s += __shfl_down_sync(0xffffffffu, s, off);
            if (lane == 0) { out[0] = (float)s; g_count = 0; }
        }
    }
}

extern "C" void kernel_launch(void* const* d_in, const int* in_sizes, int n_in,
                              void* d_out, int out_size) {
    const float* in = (const float*)d_in[0];
    const float* tg = (const float*)d_in[1];
    entropy_fused<<<NROWS, NT>>>(in, tg, (float*)d_out);
}

// round 6
// speedup vs baseline: 1.5394x; 1.1866x over previous
#include <cuda_runtime.h>

#define NROWS 128
#define LEN   2048
#define NK    6
#define NT    1024

__device__ float        g_partials[NROWS];
__device__ unsigned int g_count = 0;

__device__ __forceinline__ float4 f4add(float4 a, float4 b) {
    return make_float4(a.x + b.x, a.y + b.y, a.z + b.z, a.w + b.w);
}

__global__ void __launch_bounds__(NT, 1) entropy_fused(
    const float* __restrict__ in, const float* __restrict__ tg, float* __restrict__ out)
{
    // P[i] = inclusive prefix over elements < i of (e^a, a e^a, e^b, b e^b)
    __shared__ float4 P[LEN + 1];
    __shared__ float4 wtot[NT / 32];
    __shared__ float  redk[NT / 32];
    __shared__ int    lastFlag;

    const int tid  = threadIdx.x;
    const int lane = tid & 31, wid = tid >> 5;
    const int row  = blockIdx.x;

    // ---- 2 consecutive elements per thread ----
    const float2 a2 = ((const float2*)(in + (size_t)row * LEN))[tid];
    const float2 b2 = ((const float2*)(tg + (size_t)row * LEN))[tid];
    float e0 = __expf(a2.x), e1 = __expf(a2.y);
    float g0 = __expf(b2.x), g1 = __expf(b2.y);
    float4 v0 = make_float4(e0, a2.x * e0, g0, b2.x * g0);
    float4 v1 = f4add(make_float4(e1, a2.y * e1, g1, b2.y * g1), v0);  // local inclusive

    // warp inclusive scan of per-thread totals
    float4 t = v1;
    #pragma unroll
    for (int off = 1; off < 32; off <<= 1) {
        float4 n;
        n.x = __shfl_up_sync(0xffffffffu, t.x, off);
        n.y = __shfl_up_sync(0xffffffffu, t.y, off);
        n.z = __shfl_up_sync(0xffffffffu, t.z, off);
        n.w = __shfl_up_sync(0xffffffffu, t.w, off);
        if (lane >= off) t = f4add(t, n);
    }
    if (lane == 31) wtot[wid] = t;
    __syncthreads();
    if (wid == 0) {                 // scan 32 warp totals in one warp
        float4 w = wtot[lane];
        #pragma unroll
        for (int off = 1; off < 32; off <<= 1) {
            float4 n;
            n.x = __shfl_up_sync(0xffffffffu, w.x, off);
            n.y = __shfl_up_sync(0xffffffffu, w.y, off);
            n.z = __shfl_up_sync(0xffffffffu, w.z, off);
            n.w = __shfl_up_sync(0xffffffffu, w.w, off);
            if (lane >= off) w = f4add(w, n);
        }
        wtot[lane] = w;
    }
    __syncthreads();
    {
        float4 woff = (wid > 0) ? wtot[wid - 1] : make_float4(0.f, 0.f, 0.f, 0.f);
        float4 ex = make_float4(woff.x + t.x - v1.x, woff.y + t.y - v1.y,
                                woff.z + t.z - v1.z, woff.w + t.w - v1.w);
        P[2 * tid + 1] = f4add(v0, ex);
        P[2 * tid + 2] = f4add(v1, ex);
        if (tid == 0) P[0] = make_float4(0.f, 0.f, 0.f, 0.f);
    }
    __syncthreads();

    // ---- windows: each k has exactly <=2 windows per thread; fully unrolled ----
    // window eval: ent1 - ent2 = (S1*Z2 - S2*Z1)*r - log(Z1^2 * r), r = 1/(Z1*Z2)
    float acc = 0.0f;
    #pragma unroll
    for (int kk = 0; kk < NK; kk++) {
        const int   k  = 4 << kk;
        const int   nW = LEN - k + 1;            // 2045..1921, all > 1023
        const float wk = 1.0f / (128.0f * (float)nW);
        float acck;
        {   // window s = tid (always valid)
            float4 lo = P[tid];
            float4 hi = P[tid + k];
            float z1 = hi.x - lo.x, f1 = hi.y - lo.y;
            float z2 = hi.z - lo.z, f2 = hi.w - lo.w;
            float r = __fdividef(1.0f, z1 * z2);
            float d = fmaf(f1 * z2 - f2 * z1, r, -__logf(z1 * z1 * r));
            acck = fabsf(d);
        }
        const int s2 = tid + NT;                 // second (predicated) window
        if (s2 < nW) {
            float4 lo = P[s2];
            float4 hi = P[s2 + k];
            float z1 = hi.x - lo.x, f1 = hi.y - lo.y;
            float z2 = hi.z - lo.z, f2 = hi.w - lo.w;
            float r = __fdividef(1.0f, z1 * z2);
            float d = fmaf(f1 * z2 - f2 * z1, r, -__logf(z1 * z1 * r));
            acck += fabsf(d);
        }
        acc = fmaf(acck, wk, acc);
    }

    // ---- block reduce ----
    #pragma unroll
    for (int off = 16; off; off >>= 1) acc += __shfl_down_sync(0xffffffffu, acc, off);
    if (lane == 0) redk[wid] = acc;
    __syncthreads();
    if (wid == 0) {
        float s = redk[lane];
        #pragma unroll
        for (int off = 16; off; off >>= 1) s += __shfl_down_sync(0xffffffffu, s, off);
        if (lane == 0) {
            g_partials[row] = s;
            __threadfence();
            unsigned prev = atomicAdd(&g_count, 1u);
            lastFlag = (prev == NROWS - 1);
        }
    }
    __syncthreads();

    // ---- last block: deterministic fixed-order final sum ----
    if (lastFlag) {
        volatile const float* vp = g_partials;
        if (wid == 0) {
            double s = 0.0;
            for (int i = lane; i < NROWS; i += 32) s += (double)vp[i];
            #pragma unroll
            for (int off = 16; off; off >>= 1) s += __shfl_down_sync(0xffffffffu, s, off);
            if (lane == 0) { out[0] = (float)s; g_count = 0; }
        }
    }
}

extern "C" void kernel_launch(void* const* d_in, const int* in_sizes, int n_in,
                              void* d_out, int out_size) {
    const float* in = (const float*)d_in[0];
    const float* tg = (const float*)d_in[1];
    entropy_fused<<<NROWS, NT>>>(in, tg, (float*)d_out);
}

// round 7
// speedup vs baseline: 1.5761x; 1.0239x over previous
#include <cuda_runtime.h>

#define NROWS 128
#define LEN   2048
#define NK    6
#define NT    1024

__device__ float        g_partials[NROWS];
__device__ unsigned int g_count = 0;

__device__ __forceinline__ float4 f4add(float4 a, float4 b) {
    return make_float4(a.x + b.x, a.y + b.y, a.z + b.z, a.w + b.w);
}

__global__ void __launch_bounds__(NT, 1) entropy_fused(
    const float* __restrict__ in, const float* __restrict__ tg, float* __restrict__ out)
{
    // P[i] = inclusive prefix over elements < i of (e^a, a e^a, e^b, b e^b)
    __shared__ float4 P[LEN + 1];
    __shared__ float4 wtot[NT / 32];
    __shared__ float  redk[NT / 32];
    __shared__ int    lastFlag;

    const int tid  = threadIdx.x;
    const int lane = tid & 31, wid = tid >> 5;
    const int row  = blockIdx.x;

    // ---- 2 consecutive elements per thread ----
    const float2 a2 = ((const float2*)(in + (size_t)row * LEN))[tid];
    const float2 b2 = ((const float2*)(tg + (size_t)row * LEN))[tid];
    float e0 = __expf(a2.x), e1 = __expf(a2.y);
    float g0 = __expf(b2.x), g1 = __expf(b2.y);
    float4 v0 = make_float4(e0, a2.x * e0, g0, b2.x * g0);
    float4 v1 = f4add(make_float4(e1, a2.y * e1, g1, b2.y * g1), v0);  // local inclusive

    // warp inclusive scan of per-thread totals
    float4 t = v1;
    #pragma unroll
    for (int off = 1; off < 32; off <<= 1) {
        float4 n;
        n.x = __shfl_up_sync(0xffffffffu, t.x, off);
        n.y = __shfl_up_sync(0xffffffffu, t.y, off);
        n.z = __shfl_up_sync(0xffffffffu, t.z, off);
        n.w = __shfl_up_sync(0xffffffffu, t.w, off);
        if (lane >= off) t = f4add(t, n);
    }
    if (lane == 31) wtot[wid] = t;
    __syncthreads();
    if (wid == 0) {                 // scan 32 warp totals in one warp
        float4 w = wtot[lane];
        #pragma unroll
        for (int off = 1; off < 32; off <<= 1) {
            float4 n;
            n.x = __shfl_up_sync(0xffffffffu, w.x, off);
            n.y = __shfl_up_sync(0xffffffffu, w.y, off);
            n.z = __shfl_up_sync(0xffffffffu, w.z, off);
            n.w = __shfl_up_sync(0xffffffffu, w.w, off);
            if (lane >= off) w = f4add(w, n);
        }
        wtot[lane] = w;
    }
    __syncthreads();
    {
        float4 woff = (wid > 0) ? wtot[wid - 1] : make_float4(0.f, 0.f, 0.f, 0.f);
        float4 ex = make_float4(woff.x + t.x - v1.x, woff.y + t.y - v1.y,
                                woff.z + t.z - v1.z, woff.w + t.w - v1.w);
        P[2 * tid + 1] = f4add(v0, ex);
        P[2 * tid + 2] = f4add(v1, ex);
        if (tid == 0) P[0] = make_float4(0.f, 0.f, 0.f, 0.f);
    }
    __syncthreads();

    // ---- windows ----
    // Each thread evaluates windows s = tid (all 6 k) and s = tid+NT (where valid).
    // The lo operand is shared across all k for a given s: hoist it once.
    // ent1 - ent2 = (S1*Z2 - S2*Z1)*r - log(Z1^2 * r), r = 1/(Z1*Z2)
    const float4 lo0 = P[tid];
    const float4 lo1 = P[tid + NT];   // tid+NT <= 2047, in-bounds; used only when valid
    float acc = 0.0f;
    #pragma unroll
    for (int kk = 0; kk < NK; kk++) {
        const int   k  = 4 << kk;
        const int   nW = LEN - k + 1;            // 2045..1921, all > 1023
        const float wk = 1.0f / (128.0f * (float)nW);
        float acck;
        {   // window s = tid (always valid)
            float4 hi = P[tid + k];
            float z1 = hi.x - lo0.x, f1 = hi.y - lo0.y;
            float z2 = hi.z - lo0.z, f2 = hi.w - lo0.w;
            float r = __fdividef(1.0f, z1 * z2);
            float d = fmaf(f1 * z2 - f2 * z1, r, -__logf(z1 * z1 * r));
            acck = fabsf(d);
        }
        if (tid + NT < nW) {                     // second (predicated) window
            float4 hi = P[tid + NT + k];
            float z1 = hi.x - lo1.x, f1 = hi.y - lo1.y;
            float z2 = hi.z - lo1.z, f2 = hi.w - lo1.w;
            float r = __fdividef(1.0f, z1 * z2);
            float d = fmaf(f1 * z2 - f2 * z1, r, -__logf(z1 * z1 * r));
            acck += fabsf(d);
        }
        acc = fmaf(acck, wk, acc);
    }

    // ---- block reduce ----
    #pragma unroll
    for (int off = 16; off; off >>= 1) acc += __shfl_down_sync(0xffffffffu, acc, off);
    if (lane == 0) redk[wid] = acc;
    __syncthreads();
    if (wid == 0) {
        float s = redk[lane];
        #pragma unroll
        for (int off = 16; off; off >>= 1) s += __shfl_down_sync(0xffffffffu, s, off);
        if (lane == 0) {
            g_partials[row] = s;
            __threadfence();
            unsigned prev = atomicAdd(&g_count, 1u);
            lastFlag = (prev == NROWS - 1);
        }
    }
    __syncthreads();

    // ---- last block: deterministic fixed-order final sum ----
    if (lastFlag) {
        volatile const float* vp = g_partials;
        if (wid == 0) {
            double s = 0.0;
            for (int i = lane; i < NROWS; i += 32) s += (double)vp[i];
            #pragma unroll
            for (int off = 16; off; off >>= 1) s += __shfl_down_sync(0xffffffffu, s, off);
            if (lane == 0) { out[0] = (float)s; g_count = 0; }
        }
    }
}

extern "C" void kernel_launch(void* const* d_in, const int* in_sizes, int n_in,
                              void* d_out, int out_size) {
    const float* in = (const float*)d_in[0];
    const float* tg = (const float*)d_in[1];
    entropy_fused<<<NROWS, NT>>>(in, tg, (float*)d_out);
}